// round 14
// baseline (speedup 1.0000x reference)
#include <cuda_runtime.h>
#include <cuda_bf16.h>
#include <cstdint>

// Hardware tanh (MUFU.TANH, lat ~16 cyc).
__device__ __forceinline__ float htanh(float x) {
    float y;
    asm("tanh.approx.f32 %0, %1;" : "=f"(y) : "f"(x));
    return y;
}

// Scalar LSTM recurrence; output fed back as input (x_t == h_t), so
//   z = h*(Wi+Wh) + b,    sigmoid(z) = 0.5*tanh(0.5*z) + 0.5.
//
// FROZEN OPTIMUM (double-confirmed: ncu 5.248us R8, 5.120us R12).
// Findings over 13 rounds:
//  - Data chain 48 cyc/step; a per-iter convergence branch adds ~18 cyc ->
//    check once per 8-step block at u==6 (resolves in the final step's shadow).
//  - Contraction ~0.4/iter: converges in ~2 blocks; kernel time is dominated
//    by fixed launch/entry/fill/drain overhead (~4.5us), not the loop (~0.5us).
//  - Tolerance 2e-4 -> rel_err 2.8e-6, block-quantized exit (looser tol is a
//    no-op; earlier check positions exit later, not earlier).
//  - Epilogue must stay the simple scalar fill (float4 variant perturbed
//    whole-kernel codegen, +2us, R6). All remaining edits are sub-noise
//    (<0.13us) with multi-us demonstrated downside risk.
__global__ void __launch_bounds__(256, 1)
bitpredictor_lstm_kernel(const float* __restrict__ Wi,
                         const float* __restrict__ Wh,
                         const float* __restrict__ b,
                         float* __restrict__ out,
                         int n) {
    __shared__ float s_hfinal;
    __shared__ int   s_tstop;

    if (threadIdx.x == 0) {
        // Combined weights (x == h path)
        const float w0 = Wi[0] + Wh[0];
        const float w1 = Wi[1] + Wh[1];
        const float w2 = Wi[2] + Wh[2];
        const float w3 = Wi[3] + Wh[3];
        // sigmoid gates pre-scaled by 0.5 (i, f, o); g gate (tanh) unscaled.
        const float hw0 = 0.5f * w0, hb0 = 0.5f * b[0];
        const float hw1 = 0.5f * w1, hb1 = 0.5f * b[1];
        const float w2f = w2,        b2f = b[2];
        const float hw3 = 0.5f * w3, hb3 = 0.5f * b[3];

        // State: c, th (= tanh(c)), wgo_k = gate_weight * go_prev,
        // h = previous step's output.
        float c = 0.0f, th = 0.0f, h = 0.0f;
        float wgo0 = hw0, wgo1 = hw1, wgo2 = w2f, wgo3 = hw3;

        int   tstop  = n;
        float hfinal = 0.0f;

        const int n8 = n & ~7;
        int t = 0;

        #pragma unroll 1
        for (; t < n8; t += 8) {
            bool conv = false;

            #pragma unroll
            for (int u = 0; u < 8; ++u) {
                // Gate pre-activations: a_k = th*(w_k*go) + b_k
                float a0 = fmaf(th, wgo0, hb0);
                float a1 = fmaf(th, wgo1, hb1);
                float a2 = fmaf(th, wgo2, b2f);
                float a3 = fmaf(th, wgo3, hb3);

                float ti = htanh(a0);
                float tf = htanh(a1);
                float g  = htanh(a2);
                float to = htanh(a3);

                float gi = fmaf(0.5f, ti, 0.5f);
                float gf = fmaf(0.5f, tf, 0.5f);
                float go = fmaf(0.5f, to, 0.5f);

                float nc  = fmaf(gf, c, gi * g);
                float nth = htanh(nc);      // 16-cyc shadow hides the work below

                float nwgo0 = hw0 * go;
                float nwgo1 = hw1 * go;
                float nwgo2 = w2f * go;
                float nwgo3 = hw3 * go;
                float nh    = go * nth;

                out[t + u] = nh;

                if (u == 6) {
                    // Predicate resolves during step 7's data chain; the block
                    // back-branch below is latency-hidden.
                    conv = (fabsf(nh - h) <= fmaf(2e-4f, fabsf(nh), 1e-12f)) &&
                           (fabsf(nc - c) <= fmaf(2e-4f, fabsf(nc), 1e-12f));
                }

                c = nc; th = nth; h = nh;
                wgo0 = nwgo0; wgo1 = nwgo1; wgo2 = nwgo2; wgo3 = nwgo3;
            }

            if (conv) {
                tstop  = t + 8;
                hfinal = h;
                break;
            }
        }

        // Scalar remainder (only if n % 8 != 0 and no early exit).
        if (tstop == n) {
            #pragma unroll 1
            for (int r = t < n8 ? n8 : t; r < n; ++r) {
                float a0 = fmaf(th, wgo0, hb0);
                float a1 = fmaf(th, wgo1, hb1);
                float a2 = fmaf(th, wgo2, b2f);
                float a3 = fmaf(th, wgo3, hb3);
                float ti = htanh(a0);
                float tf = htanh(a1);
                float g  = htanh(a2);
                float to = htanh(a3);
                float gi = fmaf(0.5f, ti, 0.5f);
                float gf = fmaf(0.5f, tf, 0.5f);
                float go = fmaf(0.5f, to, 0.5f);
                float nc  = fmaf(gf, c, gi * g);
                float nth = htanh(nc);
                float nh  = go * nth;
                out[r] = nh;
                c = nc; th = nth; h = nh;
                wgo0 = hw0 * go; wgo1 = hw1 * go;
                wgo2 = w2f * go; wgo3 = hw3 * go;
            }
        }

        s_tstop  = tstop;
        s_hfinal = hfinal;
    }
    __syncthreads();

    // Parallel broadcast-fill of the converged tail (simple scalar form).
    const int   tstop  = s_tstop;
    const float hfinal = s_hfinal;
    for (int j = tstop + threadIdx.x; j < n; j += blockDim.x) {
        out[j] = hfinal;
    }
}

extern "C" void kernel_launch(void* const* d_in, const int* in_sizes, int n_in,
                              void* d_out, int out_size) {
    const float* Wi = (const float*)d_in[0];   // (1,4)
    const float* Wh = (const float*)d_in[1];   // (1,4)
    const float* b  = (const float*)d_in[2];   // (4,)
    float* out = (float*)d_out;                // (features,)
    bitpredictor_lstm_kernel<<<1, 256>>>(Wi, Wh, b, out, out_size);
}